// round 5
// baseline (speedup 1.0000x reference)
#include <cuda_runtime.h>

#define B_ 32
#define M_ 2048
#define H_ 1024
#define NTOK (B_*M_)
#define THRESH 0.99f
#define TOK_PER_BLK 32
#define BPB (M_/TOK_PER_BLK)      // 64 blocks per batch
#define NBLK (NTOK/TOK_PER_BLK)   // 2048 blocks

// Scratch (no allocations allowed).
__device__ int g_rank[NTOK];            // clip(cumsum(run)-1, 0, M-1)
__device__ unsigned char g_runb[NTOK];  // decoded run mask
__device__ int g_prefix[B_*BPB];        // inclusive run_new count + 1; 0 = not ready
__device__ unsigned int g_ticket;       // in-order virtual block ids

// ---------------------------------------------------------------------------
// K0: wire-format probe + decode + per-batch rank scan. Also resets the
// chain state (g_prefix window for this batch, g_ticket) for this replay.
// Probe: int32 {0,1} layout has no bits above the low byte in any word;
// u8 bools (~50% dense) set high bytes with prob. 1 - 2^-1536 per batch.
// ---------------------------------------------------------------------------
__global__ void rank_kernel(const void* __restrict__ run) {
    const int b = blockIdx.x;
    const int t = threadIdx.x;            // 256 threads
    const unsigned int* w = (const unsigned int*)run;

    if (t < BPB) g_prefix[b * BPB + t] = 0;
    if (b == 0 && t == 0) g_ticket = 0u;

    int found = 0;
    #pragma unroll
    for (int i = 0; i < 2; i++)
        if (w[b * 512 + i * 256 + t] & 0xFFFFFF00u) found = 1;
    const int fmt_u8 = __syncthreads_or(found);

    const unsigned char* ru8 = (const unsigned char*)run + b * M_;
    const int* ri32 = (const int*)run + b * M_;
    const int base = t * 8;

    int v[8];
    int s = 0;
    #pragma unroll
    for (int i = 0; i < 8; i++) {
        v[i] = fmt_u8 ? (ru8[base + i] != 0) : (ri32[base + i] != 0);
        s += v[i];
        g_runb[b * M_ + base + i] = (unsigned char)v[i];
    }

    const int lane = t & 31, warp = t >> 5;
    int x = s;
    #pragma unroll
    for (int o = 1; o < 32; o <<= 1) {
        int y = __shfl_up_sync(0xffffffffu, x, o);
        if (lane >= o) x += y;
    }
    __shared__ int wsum[8], woff[8];
    if (lane == 31) wsum[warp] = x;
    __syncthreads();
    if (t == 0) { int a = 0; for (int i = 0; i < 8; i++) { woff[i] = a; a += wsum[i]; } }
    __syncthreads();

    int c = woff[warp] + (x - s);
    #pragma unroll
    for (int i = 0; i < 8; i++) {
        c += v[i];
        int rk = c - 1;
        if (rk < 0) rk = 0;
        g_rank[b * M_ + base + i] = rk;
    }
}

// ---------------------------------------------------------------------------
// K1: fully fused. Per block: 32 tokens of one batch.
//  Phase 1: warp-per-token dots -> p, p_adj, run_new (into smem), acc_out.
//  Chain:   block scan of run_new; ticket-ordered spin on predecessor block's
//           inclusive prefix; publish own. Gives every token its global
//           exclusive run_new prefix -> packed destination:
//             run_new:  dest = prefix(run_new)                (front-fill)
//             else:     dest = M-1 - (pos - prefix(run_new))  (back-fill, zero)
//  Phase 3: reload h row (hot in L1/L2), write weighted blend AND its packed
//           row (data or zeros). Every packed row written exactly once.
// ---------------------------------------------------------------------------
__global__ __launch_bounds__(128) void main_kernel(
    const float* __restrict__ h, const float* __restrict__ W,
    const float* __restrict__ bias, const float* __restrict__ wh,
    const float* __restrict__ accp,
    float* __restrict__ packed, float* __restrict__ weighted_out,
    float* __restrict__ acc_out)
{
    __shared__ float sW[H_];
    __shared__ float s_padj[TOK_PER_BLK];
    __shared__ int   s_run[TOK_PER_BLK];
    __shared__ int   s_lexcl[TOK_PER_BLK];
    __shared__ int   s_base;
    __shared__ unsigned int s_vid;

    const int tid = threadIdx.x;
    #pragma unroll
    for (int i = 0; i < 2; i++)
        ((float4*)sW)[tid + i * 128] = ((const float4*)W)[tid + i * 128];
    if (tid == 0) s_vid = atomicAdd(&g_ticket, 1u);
    __syncthreads();

    const int vid   = (int)s_vid;          // ticket order == scheduling order
    const int batch = vid / BPB;
    const int bpos  = vid % BPB;
    const int tok0  = batch * M_ + bpos * TOK_PER_BLK;
    const int warp = tid >> 5, lane = tid & 31;
    const float bv = bias[0];

    // ---- phase 1: dots (8 tokens per warp) ----
    #pragma unroll
    for (int k = 0; k < 8; k++) {
        const int t = warp * 8 + k;
        const int tok = tok0 + t;
        const bool running = g_runb[tok] != 0;
        const int rank = g_rank[tok];
        float dot = 0.0f;
        if (running) {
            const float4* hrow = (const float4*)(h + ((size_t)batch * M_ + rank) * H_);
            #pragma unroll
            for (int i = 0; i < 8; i++) {
                float4 a  = hrow[lane + i * 32];
                float4 wv = ((const float4*)sW)[lane + i * 32];
                dot += a.x * wv.x + a.y * wv.y + a.z * wv.z + a.w * wv.w;
            }
        }
        #pragma unroll
        for (int o = 16; o > 0; o >>= 1)
            dot += __shfl_xor_sync(0xffffffffu, dot, o);
        if (lane == 0) {
            float acc = accp[tok];
            float p_adj = 0.0f;
            int run_new = 0;
            if (running) {
                float p = 1.0f / (1.0f + expf(-(dot + bv)));
                float an = acc + p;
                run_new = an < THRESH;
                p_adj = run_new ? p : (1.0f - (an - p));
                acc = an;
            }
            acc_out[tok] = acc;
            s_padj[t] = p_adj;
            s_run[t]  = run_new;
        }
    }
    __syncthreads();

    // ---- chain: block scan + ordered publish ----
    if (warp == 0) {
        int v = s_run[lane];
        int x = v;
        #pragma unroll
        for (int o = 1; o < 32; o <<= 1) {
            int y = __shfl_up_sync(0xffffffffu, x, o);
            if (lane >= o) x += y;
        }
        s_lexcl[lane] = x - v;
        if (lane == 31) {
            const int total = x;
            int base = 0;
            if (bpos > 0) {
                volatile int* pp = (volatile int*)&g_prefix[batch * BPB + bpos - 1];
                int got;
                do { got = *pp; } while (got == 0);
                base = got - 1;
            }
            *(volatile int*)&g_prefix[batch * BPB + bpos] = base + total + 1;
            s_base = base;
        }
    }
    __syncthreads();
    const int base = s_base;

    // ---- phase 3: blend + weighted + packed ----
    #pragma unroll
    for (int k = 0; k < 8; k++) {
        const int t = warp * 8 + k;
        const int tok = tok0 + t;
        const bool running = g_runb[tok] != 0;
        const int rank = g_rank[tok];
        const float p_adj = s_padj[t];
        const int runnew = s_run[t];
        const int cumexcl = base + s_lexcl[t];
        const int pos = bpos * TOK_PER_BLK + t;
        const int dest = runnew ? cumexcl : (M_ - 1 - (pos - cumexcl));
        const float q = 1.0f - p_adj;

        const float4* hrow  = (const float4*)(h  + ((size_t)batch * M_ + rank) * H_);
        const float4* whrow = (const float4*)(wh + (size_t)tok * H_);
        float4* wo = (float4*)(weighted_out + (size_t)tok * H_);
        float4* po = (float4*)(packed + ((size_t)batch * M_ + dest) * H_);
        const float4 z = make_float4(0.f, 0.f, 0.f, 0.f);

        #pragma unroll
        for (int i = 0; i < 8; i++) {
            float4 a  = running ? hrow[lane + i * 32] : z;
            float4 w4 = whrow[lane + i * 32];
            float4 o4;
            o4.x = a.x * p_adj + w4.x * q;
            o4.y = a.y * p_adj + w4.y * q;
            o4.z = a.z * p_adj + w4.z * q;
            o4.w = a.w * p_adj + w4.w * q;
            wo[lane + i * 32] = o4;
            po[lane + i * 32] = runnew ? a : z;
        }
    }
}

// ---------------------------------------------------------------------------
extern "C" void kernel_launch(void* const* d_in, const int* in_sizes, int n_in,
                              void* d_out, int out_size) {
    const float* h    = (const float*)d_in[0];
    const float* W    = (const float*)d_in[1];
    const float* bias = (const float*)d_in[2];
    const float* wh   = (const float*)d_in[3];
    const float* accp = (const float*)d_in[4];
    const void*  run  = d_in[5];

    float* out      = (float*)d_out;
    float* packed   = out;                              // [B,M,H]
    float* weighted = out + (size_t)NTOK * H_;          // [B,M,H]
    float* acc      = out + 2 * (size_t)NTOK * H_;      // [B,M,1]

    rank_kernel<<<B_, 256>>>(run);
    main_kernel<<<NBLK, 128>>>(h, W, bias, wh, accp, packed, weighted, acc);
}

// round 6
// speedup vs baseline: 1.1442x; 1.1442x over previous
#include <cuda_runtime.h>

#define B_ 32
#define M_ 2048
#define H_ 1024
#define NTOK (B_*M_)
#define THRESH 0.99f
#define BLOCKS_PER_BATCH (M_/4)   // main: 4 tokens per block -> 512 blocks/batch

// Scratch (no allocations allowed).
__device__ int g_src[NTOK];    // run_new ? rank : -1
__device__ int g_gidx[NTOK];   // packed row d -> source row in h, -1 => zero row
__device__ int g_done[B_];     // per-batch completion counters (zero-init; compactor resets)

// ---------------------------------------------------------------------------
// K1: one kernel does everything except the final pack gather.
// Per block (4 tokens of one batch, warp-per-token):
//  (a) wire-format probe of `run`: read words [0,512) (2KB, L2-broadcast).
//      int32 {0,1} wire => no bits above the low byte; u8 bools (~50% dense
//      over 2048 tokens) => high bytes present with prob 1 - 2^-1536.
//  (b) rank: block-reduce count of running tokens in run[batch, 0..bpos*4),
//      then tiny serial cumsum over this block's 4 mask values.
//  (c) dot(h[rank], W) -> sigmoid -> p_adj / run_new / acc_new.
//  (d) weighted blend from the registers already holding the h row.
//  (e) last-arriving block per batch compacts g_src -> g_gidx (stable), then
//      resets g_done[b] for the next graph replay.
// ---------------------------------------------------------------------------
__global__ __launch_bounds__(128) void main_kernel(
    const float* __restrict__ h, const float* __restrict__ W,
    const float* __restrict__ bias, const float* __restrict__ wh,
    const float* __restrict__ accp, const void* __restrict__ run,
    float* __restrict__ weighted_out, float* __restrict__ acc_out)
{
    __shared__ float sW[H_];
    const int tid = threadIdx.x;
    const int warp = tid >> 5, lane = tid & 31;
    ((float4*)sW)[tid]       = ((const float4*)W)[tid];
    ((float4*)sW)[tid + 128] = ((const float4*)W)[tid + 128];

    const int batch = blockIdx.x >> 9;          // /512
    const int bpos  = blockIdx.x & 511;
    const int tok0  = batch * M_ + bpos * 4;

    // ---- (a) format probe: fixed 512-word window, identical for all blocks
    const unsigned int* wr = (const unsigned int*)run;
    int found = 0;
    #pragma unroll
    for (int i = 0; i < 4; i++)
        if (wr[tid + i * 128] & 0xFFFFFF00u) found = 1;
    const int fmt_u8 = __syncthreads_or(found);

    // ---- (b) prefix count of running tokens before this block's 4 tokens
    int cnt = 0;
    if (fmt_u8) {
        const unsigned int* rw = (const unsigned int*)((const unsigned char*)run + batch * M_);
        for (int i = tid; i < bpos; i += 128) {
            unsigned int w = rw[i];                       // 4 bools per word
            cnt += ((w & 0x000000FFu) != 0) + ((w & 0x0000FF00u) != 0)
                 + ((w & 0x00FF0000u) != 0) + ((w & 0xFF000000u) != 0);
        }
    } else {
        const int4* ri = (const int4*)((const int*)run + batch * M_);
        for (int i = tid; i < bpos; i += 128) {
            int4 v = ri[i];
            cnt += (v.x != 0) + (v.y != 0) + (v.z != 0) + (v.w != 0);
        }
    }
    #pragma unroll
    for (int o = 16; o > 0; o >>= 1)
        cnt += __shfl_xor_sync(0xffffffffu, cnt, o);
    __shared__ int s_ws[4];
    if (lane == 0) s_ws[warp] = cnt;
    __syncthreads();
    const int base_cnt = s_ws[0] + s_ws[1] + s_ws[2] + s_ws[3];

    // this block's 4 mask values + ranks (every thread computes all 4)
    int v4[4];
    if (fmt_u8) {
        unsigned int w4 = *(const unsigned int*)((const unsigned char*)run + batch * M_ + bpos * 4);
        v4[0] = (w4 & 0x000000FFu) != 0; v4[1] = (w4 & 0x0000FF00u) != 0;
        v4[2] = (w4 & 0x00FF0000u) != 0; v4[3] = (w4 & 0xFF000000u) != 0;
    } else {
        int4 t4 = ((const int4*)((const int*)run + batch * M_))[bpos];
        v4[0] = t4.x != 0; v4[1] = t4.y != 0; v4[2] = t4.z != 0; v4[3] = t4.w != 0;
    }
    int rk[4];
    {
        int c = base_cnt;
        #pragma unroll
        for (int t = 0; t < 4; t++) {
            c += v4[t];
            rk[t] = (c - 1 < 0) ? 0 : (c - 1);
        }
    }

    // ---- (c) warp-per-token dot + halting scalars
    const int tok = tok0 + warp;
    const bool running = v4[warp] != 0;
    const int rank = rk[warp];

    float4 hv[8];
    float dot = 0.0f;
    if (running) {
        const float4* hrow = (const float4*)(h + ((size_t)batch * M_ + rank) * H_);
        #pragma unroll
        for (int i = 0; i < 8; i++) {
            float4 a = hrow[lane + i * 32];
            hv[i] = a;
            float4 wv = ((const float4*)sW)[lane + i * 32];
            dot += a.x * wv.x + a.y * wv.y + a.z * wv.z + a.w * wv.w;
        }
    } else {
        #pragma unroll
        for (int i = 0; i < 8; i++) hv[i] = make_float4(0.f, 0.f, 0.f, 0.f);
    }
    #pragma unroll
    for (int o = 16; o > 0; o >>= 1)
        dot += __shfl_xor_sync(0xffffffffu, dot, o);

    float acc = accp[tok];
    float p_adj = 0.0f;
    bool run_new = false;
    if (running) {
        float z = dot + bias[0];
        float p = 1.0f / (1.0f + expf(-z));
        float an = acc + p;
        run_new = an < THRESH;
        p_adj = run_new ? p : (1.0f - (an - p));
        acc = an;
    }
    if (lane == 0) {
        acc_out[tok] = acc;
        g_src[tok] = run_new ? rank : -1;
    }

    // ---- (d) weighted blend (h row still in registers)
    const float4* whrow = (const float4*)(wh + (size_t)tok * H_);
    float4* wo = (float4*)(weighted_out + (size_t)tok * H_);
    const float q = 1.0f - p_adj;
    #pragma unroll
    for (int i = 0; i < 8; i++) {
        float4 w4 = whrow[lane + i * 32];
        float4 o4;
        o4.x = hv[i].x * p_adj + w4.x * q;
        o4.y = hv[i].y * p_adj + w4.y * q;
        o4.z = hv[i].z * p_adj + w4.z * q;
        o4.w = hv[i].w * p_adj + w4.w * q;
        wo[lane + i * 32] = o4;
    }

    // ---- (e) fused per-batch compaction: last-arriving block does the scan
    __shared__ int s_last;
    __syncthreads();
    if (tid == 0) {
        __threadfence();                 // release g_src to other SMs
        int n = atomicAdd(&g_done[batch], 1);
        s_last = (n == BLOCKS_PER_BATCH - 1);
    }
    __syncthreads();
    if (!s_last) return;

    const int cbase = batch * M_ + tid * 16;
    int src[16], cv[16];
    int s = 0;
    #pragma unroll
    for (int i = 0; i < 16; i++) {
        src[i] = g_src[cbase + i];
        cv[i] = (src[i] >= 0) ? 1 : 0;
        s += cv[i];
        g_gidx[cbase + i] = -1;          // default: zero row
    }
    int x = s;
    #pragma unroll
    for (int o = 1; o < 32; o <<= 1) {
        int y = __shfl_up_sync(0xffffffffu, x, o);
        if (lane >= o) x += y;
    }
    __shared__ int cw[4], co[4];
    if (lane == 31) cw[warp] = x;
    __syncthreads();
    if (tid == 0) {
        int a = 0;
        for (int i = 0; i < 4; i++) { co[i] = a; a += cw[i]; }
        g_done[batch] = 0;               // reset for next graph replay
    }
    __syncthreads();                     // orders the -1 init before scatter

    int pos = co[warp] + (x - s);
    #pragma unroll
    for (int i = 0; i < 16; i++) {
        if (cv[i]) {
            g_gidx[batch * M_ + pos] = src[i];
            pos++;
        }
    }
}

// ---------------------------------------------------------------------------
// K3: packed[b,d,:] = gidx>=0 ? h[b,gidx,:] : 0. Warp-per-row gather.
// ---------------------------------------------------------------------------
__global__ __launch_bounds__(128) void pack_kernel(const float* __restrict__ h,
                                                   float* __restrict__ packed)
{
    const int warp = threadIdx.x >> 5, lane = threadIdx.x & 31;
    const int tok = blockIdx.x * 4 + warp;
    const int b = tok >> 11;
    const int g = g_gidx[tok];

    float4* out = (float4*)(packed + (size_t)tok * H_);
    if (g >= 0) {
        const float4* hrow = (const float4*)(h + ((size_t)b * M_ + g) * H_);
        #pragma unroll
        for (int i = 0; i < 8; i++) out[lane + i * 32] = hrow[lane + i * 32];
    } else {
        const float4 z = make_float4(0.f, 0.f, 0.f, 0.f);
        #pragma unroll
        for (int i = 0; i < 8; i++) out[lane + i * 32] = z;
    }
}

// ---------------------------------------------------------------------------
extern "C" void kernel_launch(void* const* d_in, const int* in_sizes, int n_in,
                              void* d_out, int out_size) {
    const float* h    = (const float*)d_in[0];
    const float* W    = (const float*)d_in[1];
    const float* bias = (const float*)d_in[2];
    const float* wh   = (const float*)d_in[3];
    const float* accp = (const float*)d_in[4];
    const void*  run  = d_in[5];

    float* out      = (float*)d_out;
    float* packed   = out;                              // [B,M,H]
    float* weighted = out + (size_t)NTOK * H_;          // [B,M,H]
    float* acc      = out + 2 * (size_t)NTOK * H_;      // [B,M,1]

    main_kernel<<<NTOK / 4, 128>>>(h, W, bias, wh, accp, run, weighted, acc);
    pack_kernel<<<NTOK / 4, 128>>>(h, packed);
}

// round 7
// speedup vs baseline: 1.1740x; 1.0261x over previous
#include <cuda_runtime.h>

#define B_ 32
#define M_ 2048
#define H_ 1024
#define NTOK (B_*M_)
#define THRESH 0.99f
#define BLOCKS_PER_BATCH (M_/4)   // main: 4 tokens per block

// Scratch (no allocations allowed).
__device__ int g_rank[NTOK];          // clip(cumsum(run)-1, 0, M-1)
__device__ unsigned char g_runb[NTOK];// decoded run mask
__device__ int g_src[NTOK];           // run_new ? rank : -1
__device__ int g_gidx[NTOK];          // packed row d -> source row in h, -1 => zero row
__device__ int g_done[B_];            // per-batch completion counters (reset each call)

// ---------------------------------------------------------------------------
// K0: wire-format probe + decode + per-batch rank scan, fused. Also resets
// this batch's g_done counter for the fused compaction in main_kernel.
// Probe: read this block's 512-word window of `run` as u32. int32 {0,1} =>
// no bits above the low byte anywhere; u8 bools (~50% ones) => high bytes
// present with probability 1 - 2^-1536.
// ---------------------------------------------------------------------------
__global__ void rank_kernel(const void* __restrict__ run) {
    const int b = blockIdx.x;
    const int t = threadIdx.x;            // 256 threads
    const unsigned int* w = (const unsigned int*)run;

    if (t == 0) g_done[b] = 0;

    int found = 0;
    #pragma unroll
    for (int i = 0; i < 2; i++)
        if (w[b * 512 + i * 256 + t] & 0xFFFFFF00u) found = 1;
    const int fmt_u8 = __syncthreads_or(found);

    const unsigned char* ru8 = (const unsigned char*)run + b * M_;
    const int* ri32 = (const int*)run + b * M_;
    const int base = t * 8;

    int v[8];
    int s = 0;
    #pragma unroll
    for (int i = 0; i < 8; i++) {
        v[i] = fmt_u8 ? (ru8[base + i] != 0) : (ri32[base + i] != 0);
        s += v[i];
        g_runb[b * M_ + base + i] = (unsigned char)v[i];
    }

    const int lane = t & 31, warp = t >> 5;
    int x = s;  // inclusive warp scan of per-thread sums
    #pragma unroll
    for (int o = 1; o < 32; o <<= 1) {
        int y = __shfl_up_sync(0xffffffffu, x, o);
        if (lane >= o) x += y;
    }
    __shared__ int wsum[8], woff[8];
    if (lane == 31) wsum[warp] = x;
    __syncthreads();
    if (t == 0) { int a = 0; for (int i = 0; i < 8; i++) { woff[i] = a; a += wsum[i]; } }
    __syncthreads();

    int c = woff[warp] + (x - s);
    #pragma unroll
    for (int i = 0; i < 8; i++) {
        c += v[i];
        int rk = c - 1;
        if (rk < 0) rk = 0;
        g_rank[b * M_ + base + i] = rk;
    }
}

// ---------------------------------------------------------------------------
// K1: warp-per-token (4 warps / 128 threads). Dot(h[rank], W) -> sigmoid ->
// halting scalars -> weighted_new blend from registers. Tail: last block per
// batch runs that batch's stable compaction (g_src -> g_gidx).
// ---------------------------------------------------------------------------
__global__ __launch_bounds__(128) void main_kernel(
    const float* __restrict__ h, const float* __restrict__ W,
    const float* __restrict__ bias, const float* __restrict__ wh,
    const float* __restrict__ accp,
    float* __restrict__ weighted_out, float* __restrict__ acc_out)
{
    __shared__ float sW[H_];
    for (int i = threadIdx.x; i < H_ / 4; i += 128)
        ((float4*)sW)[i] = ((const float4*)W)[i];
    __syncthreads();

    const int warp = threadIdx.x >> 5, lane = threadIdx.x & 31;
    const int tok = blockIdx.x * 4 + warp;
    const int b = tok >> 11;               // uniform per block (4 | 2048)
    const bool running = g_runb[tok] != 0;
    const int rank = g_rank[tok];

    float4 hv[8];
    float dot = 0.0f;
    if (running) {
        const float4* hrow = (const float4*)(h + ((size_t)b * M_ + rank) * H_);
        #pragma unroll
        for (int i = 0; i < 8; i++) {
            float4 a = hrow[lane + i * 32];
            hv[i] = a;
            float4 wv = ((const float4*)sW)[lane + i * 32];
            dot += a.x * wv.x;
            dot += a.y * wv.y;
            dot += a.z * wv.z;
            dot += a.w * wv.w;
        }
    } else {
        #pragma unroll
        for (int i = 0; i < 8; i++) hv[i] = make_float4(0.f, 0.f, 0.f, 0.f);
    }
    #pragma unroll
    for (int o = 16; o > 0; o >>= 1)
        dot += __shfl_xor_sync(0xffffffffu, dot, o);

    float acc = accp[tok];
    float p_adj = 0.0f;
    bool run_new = false;
    if (running) {
        float z = dot + bias[0];
        float p = 1.0f / (1.0f + expf(-z));
        float acc_new = acc + p;
        run_new = acc_new < THRESH;
        p_adj = run_new ? p : (1.0f - (acc_new - p));
        acc = acc_new;
    }
    if (lane == 0) {
        acc_out[tok] = acc;
        g_src[tok] = run_new ? rank : -1;
    }

    const float4* whrow = (const float4*)(wh + (size_t)tok * H_);
    float4* wo = (float4*)(weighted_out + (size_t)tok * H_);
    const float q = 1.0f - p_adj;
    #pragma unroll
    for (int i = 0; i < 8; i++) {
        float4 w4 = whrow[lane + i * 32];
        float4 o4;
        o4.x = hv[i].x * p_adj + w4.x * q;
        o4.y = hv[i].y * p_adj + w4.y * q;
        o4.z = hv[i].z * p_adj + w4.z * q;
        o4.w = hv[i].w * p_adj + w4.w * q;
        wo[lane + i * 32] = o4;
    }

    // ---- fused per-batch compaction: last-arriving block does the scan ----
    __shared__ int s_last;
    __syncthreads();                 // all warps' g_src writes issued
    if (threadIdx.x == 0) {
        __threadfence();             // release g_src to other SMs
        int n = atomicAdd(&g_done[b], 1);
        s_last = (n == BLOCKS_PER_BATCH - 1);
    }
    __syncthreads();
    if (!s_last) return;

    // This block compacts batch b: 2048 elements, 128 threads, 16 per thread.
    const int t = threadIdx.x;
    const int base = b * M_ + t * 16;
    int src[16], v[16];
    int s = 0;
    #pragma unroll
    for (int i = 0; i < 16; i++) {
        src[i] = g_src[base + i];
        v[i] = (src[i] >= 0) ? 1 : 0;
        s += v[i];
        g_gidx[base + i] = -1;       // default: zero row
    }
    int x = s;
    #pragma unroll
    for (int o = 1; o < 32; o <<= 1) {
        int y = __shfl_up_sync(0xffffffffu, x, o);
        if (lane >= o) x += y;
    }
    __shared__ int cw[4], co[4];
    if (lane == 31) cw[warp] = x;
    __syncthreads();
    if (t == 0) { int a = 0; for (int i = 0; i < 4; i++) { co[i] = a; a += cw[i]; } }
    __syncthreads();                 // also orders the -1 init before scatter

    int pos = co[warp] + (x - s);    // exclusive prefix = destination slot
    #pragma unroll
    for (int i = 0; i < 16; i++) {
        if (v[i]) {
            g_gidx[b * M_ + pos] = src[i];
            pos++;
        }
    }
}

// ---------------------------------------------------------------------------
// K3: packed[b,d,:] = gidx>=0 ? h[b,gidx,:] : 0. Warp-per-row gather with
// all 8 float4 loads batched before the stores (MLP_p1 = 8 instead of ~4;
// pack was latency-shaped: issue=3.2%, DRAM=67.7%).
// ---------------------------------------------------------------------------
__global__ __launch_bounds__(128) void pack_kernel(const float* __restrict__ h,
                                                   float* __restrict__ packed)
{
    const int warp = threadIdx.x >> 5, lane = threadIdx.x & 31;
    const int tok = blockIdx.x * 4 + warp;
    const int b = tok >> 11;
    const int g = g_gidx[tok];

    float4* out = (float4*)(packed + (size_t)tok * H_);
    if (g >= 0) {
        const float4* hrow = (const float4*)(h + ((size_t)b * M_ + g) * H_);
        float4 r[8];
        #pragma unroll
        for (int i = 0; i < 8; i++) r[i] = hrow[lane + i * 32];   // all loads in flight
        #pragma unroll
        for (int i = 0; i < 8; i++) out[lane + i * 32] = r[i];
    } else {
        const float4 z = make_float4(0.f, 0.f, 0.f, 0.f);
        #pragma unroll
        for (int i = 0; i < 8; i++) out[lane + i * 32] = z;
    }
}

// ---------------------------------------------------------------------------
extern "C" void kernel_launch(void* const* d_in, const int* in_sizes, int n_in,
                              void* d_out, int out_size) {
    const float* h    = (const float*)d_in[0];
    const float* W    = (const float*)d_in[1];
    const float* bias = (const float*)d_in[2];
    const float* wh   = (const float*)d_in[3];
    const float* accp = (const float*)d_in[4];
    const void*  run  = d_in[5];

    float* out      = (float*)d_out;
    float* packed   = out;                              // [B,M,H]
    float* weighted = out + (size_t)NTOK * H_;          // [B,M,H]
    float* acc      = out + 2 * (size_t)NTOK * H_;      // [B,M,1]

    rank_kernel<<<B_, 256>>>(run);
    main_kernel<<<NTOK / 4, 128>>>(h, W, bias, wh, accp, weighted, acc);
    pack_kernel<<<NTOK / 4, 128>>>(h, packed);
}

// round 8
// speedup vs baseline: 1.1779x; 1.0033x over previous
#include <cuda_runtime.h>

#define B_ 32
#define M_ 2048
#define H_ 1024
#define NTOK (B_*M_)
#define THRESH 0.99f
#define BLOCKS_PER_BATCH (M_/4)   // main: 4 tokens per block

// Scratch (no allocations allowed).
__device__ int g_rank[NTOK];          // clip(cumsum(run)-1, 0, M-1)
__device__ unsigned char g_runb[NTOK];// decoded run mask
__device__ int g_src[NTOK];           // run_new ? rank : -1
__device__ int g_gidx[NTOK];          // packed row d -> source row in h, -1 => zero row
__device__ int g_done[B_];            // per-batch completion counters (reset each call)

// ---------------------------------------------------------------------------
// K0: wire-format probe + decode + per-batch rank scan. Both format
// interpretations are loaded BEFORE the probe resolves (independent loads in
// flight together) to cut one serial DRAM round-trip off the critical path.
// ---------------------------------------------------------------------------
__global__ void rank_kernel(const void* __restrict__ run) {
    const int b = blockIdx.x;
    const int t = threadIdx.x;            // 256 threads
    const unsigned int* w = (const unsigned int*)run;

    if (t == 0) g_done[b] = 0;

    // issue everything up front: probe words + u8 view + i32 view
    unsigned int p0 = w[b * 512 + t];
    unsigned int p1 = w[b * 512 + 256 + t];
    const int base = t * 8;
    uint2 u8v = *(const uint2*)((const unsigned char*)run + b * M_ + base);
    int4 i0 = ((const int4*)((const int*)run + b * M_ + base))[0];
    int4 i1 = ((const int4*)((const int*)run + b * M_ + base))[1];

    int found = ((p0 | p1) & 0xFFFFFF00u) ? 1 : 0;
    const int fmt_u8 = __syncthreads_or(found);

    int v[8];
    if (fmt_u8) {
        v[0] = (u8v.x & 0x000000FFu) != 0; v[1] = (u8v.x & 0x0000FF00u) != 0;
        v[2] = (u8v.x & 0x00FF0000u) != 0; v[3] = (u8v.x & 0xFF000000u) != 0;
        v[4] = (u8v.y & 0x000000FFu) != 0; v[5] = (u8v.y & 0x0000FF00u) != 0;
        v[6] = (u8v.y & 0x00FF0000u) != 0; v[7] = (u8v.y & 0xFF000000u) != 0;
    } else {
        v[0] = i0.x != 0; v[1] = i0.y != 0; v[2] = i0.z != 0; v[3] = i0.w != 0;
        v[4] = i1.x != 0; v[5] = i1.y != 0; v[6] = i1.z != 0; v[7] = i1.w != 0;
    }
    int s = 0;
    #pragma unroll
    for (int i = 0; i < 8; i++) {
        s += v[i];
        g_runb[b * M_ + base + i] = (unsigned char)v[i];
    }

    const int lane = t & 31, warp = t >> 5;
    int x = s;  // inclusive warp scan of per-thread sums
    #pragma unroll
    for (int o = 1; o < 32; o <<= 1) {
        int y = __shfl_up_sync(0xffffffffu, x, o);
        if (lane >= o) x += y;
    }
    __shared__ int wsum[8], woff[8];
    if (lane == 31) wsum[warp] = x;
    __syncthreads();
    if (t == 0) { int a = 0; for (int i = 0; i < 8; i++) { woff[i] = a; a += wsum[i]; } }
    __syncthreads();

    int c = woff[warp] + (x - s);
    #pragma unroll
    for (int i = 0; i < 8; i++) {
        c += v[i];
        int rk = c - 1;
        if (rk < 0) rk = 0;
        g_rank[b * M_ + base + i] = rk;
    }
}

// ---------------------------------------------------------------------------
// K1: warp-per-token (4 warps / 128 threads). PDL: the W->smem prologue runs
// while rank_kernel is still executing; cudaGridDependencySynchronize() gates
// the first read of rank's outputs. Tail: last block per batch compacts.
// ---------------------------------------------------------------------------
__global__ __launch_bounds__(128) void main_kernel(
    const float* __restrict__ h, const float* __restrict__ W,
    const float* __restrict__ bias, const float* __restrict__ wh,
    const float* __restrict__ accp,
    float* __restrict__ weighted_out, float* __restrict__ acc_out)
{
    __shared__ float sW[H_];
    for (int i = threadIdx.x; i < H_ / 4; i += 128)
        ((float4*)sW)[i] = ((const float4*)W)[i];

    cudaGridDependencySynchronize();   // rank_kernel writes now visible
    __syncthreads();

    const int warp = threadIdx.x >> 5, lane = threadIdx.x & 31;
    const int tok = blockIdx.x * 4 + warp;
    const int b = tok >> 11;               // uniform per block (4 | 2048)
    const bool running = g_runb[tok] != 0;
    const int rank = g_rank[tok];

    float4 hv[8];
    float dot = 0.0f;
    if (running) {
        const float4* hrow = (const float4*)(h + ((size_t)b * M_ + rank) * H_);
        #pragma unroll
        for (int i = 0; i < 8; i++) {
            float4 a = hrow[lane + i * 32];
            hv[i] = a;
            float4 wv = ((const float4*)sW)[lane + i * 32];
            dot += a.x * wv.x;
            dot += a.y * wv.y;
            dot += a.z * wv.z;
            dot += a.w * wv.w;
        }
    } else {
        #pragma unroll
        for (int i = 0; i < 8; i++) hv[i] = make_float4(0.f, 0.f, 0.f, 0.f);
    }
    #pragma unroll
    for (int o = 16; o > 0; o >>= 1)
        dot += __shfl_xor_sync(0xffffffffu, dot, o);

    float acc = accp[tok];
    float p_adj = 0.0f;
    bool run_new = false;
    if (running) {
        float z = dot + bias[0];
        float p = 1.0f / (1.0f + expf(-z));
        float acc_new = acc + p;
        run_new = acc_new < THRESH;
        p_adj = run_new ? p : (1.0f - (acc_new - p));
        acc = acc_new;
    }
    if (lane == 0) {
        acc_out[tok] = acc;
        g_src[tok] = run_new ? rank : -1;
    }

    const float4* whrow = (const float4*)(wh + (size_t)tok * H_);
    float4* wo = (float4*)(weighted_out + (size_t)tok * H_);
    const float q = 1.0f - p_adj;
    #pragma unroll
    for (int i = 0; i < 8; i++) {
        float4 w4 = whrow[lane + i * 32];
        float4 o4;
        o4.x = hv[i].x * p_adj + w4.x * q;
        o4.y = hv[i].y * p_adj + w4.y * q;
        o4.z = hv[i].z * p_adj + w4.z * q;
        o4.w = hv[i].w * p_adj + w4.w * q;
        wo[lane + i * 32] = o4;
    }

    // ---- fused per-batch compaction: last-arriving block does the scan ----
    __shared__ int s_last;
    __syncthreads();                 // all warps' g_src writes issued
    if (threadIdx.x == 0) {
        __threadfence();             // release g_src to other SMs
        int n = atomicAdd(&g_done[b], 1);
        s_last = (n == BLOCKS_PER_BATCH - 1);
    }
    __syncthreads();
    if (!s_last) return;

    const int t = threadIdx.x;
    const int base = b * M_ + t * 16;
    int src[16], v[16];
    int s = 0;
    #pragma unroll
    for (int i = 0; i < 16; i++) {
        src[i] = g_src[base + i];
        v[i] = (src[i] >= 0) ? 1 : 0;
        s += v[i];
        g_gidx[base + i] = -1;       // default: zero row
    }
    int x = s;
    #pragma unroll
    for (int o = 1; o < 32; o <<= 1) {
        int y = __shfl_up_sync(0xffffffffu, x, o);
        if (lane >= o) x += y;
    }
    __shared__ int cw[4], co[4];
    if (lane == 31) cw[warp] = x;
    __syncthreads();
    if (t == 0) { int a = 0; for (int i = 0; i < 4; i++) { co[i] = a; a += cw[i]; } }
    __syncthreads();                 // also orders the -1 init before scatter

    int pos = co[warp] + (x - s);
    #pragma unroll
    for (int i = 0; i < 16; i++) {
        if (v[i]) {
            g_gidx[b * M_ + pos] = src[i];
            pos++;
        }
    }
}

// ---------------------------------------------------------------------------
// K3: packed[b,d,:] = gidx>=0 ? h[b,gidx,:] : 0. Warp-per-row gather,
// batched loads (R7 body). PDL hides the launch gap behind main's tail.
// ---------------------------------------------------------------------------
__global__ __launch_bounds__(128) void pack_kernel(const float* __restrict__ h,
                                                   float* __restrict__ packed)
{
    cudaGridDependencySynchronize();   // main_kernel writes (g_gidx) visible

    const int warp = threadIdx.x >> 5, lane = threadIdx.x & 31;
    const int tok = blockIdx.x * 4 + warp;
    const int b = tok >> 11;
    const int g = g_gidx[tok];

    float4* out = (float4*)(packed + (size_t)tok * H_);
    if (g >= 0) {
        const float4* hrow = (const float4*)(h + ((size_t)b * M_ + g) * H_);
        float4 r[8];
        #pragma unroll
        for (int i = 0; i < 8; i++) r[i] = hrow[lane + i * 32];
        #pragma unroll
        for (int i = 0; i < 8; i++) out[lane + i * 32] = r[i];
    } else {
        const float4 z = make_float4(0.f, 0.f, 0.f, 0.f);
        #pragma unroll
        for (int i = 0; i < 8; i++) out[lane + i * 32] = z;
    }
}

// ---------------------------------------------------------------------------
extern "C" void kernel_launch(void* const* d_in, const int* in_sizes, int n_in,
                              void* d_out, int out_size) {
    const float* h    = (const float*)d_in[0];
    const float* W    = (const float*)d_in[1];
    const float* bias = (const float*)d_in[2];
    const float* wh   = (const float*)d_in[3];
    const float* accp = (const float*)d_in[4];
    const void*  run  = d_in[5];

    float* out      = (float*)d_out;
    float* packed   = out;                              // [B,M,H]
    float* weighted = out + (size_t)NTOK * H_;          // [B,M,H]
    float* acc      = out + 2 * (size_t)NTOK * H_;      // [B,M,1]

    rank_kernel<<<B_, 256>>>(run);

    cudaLaunchAttribute attr[1];
    attr[0].id = cudaLaunchAttributeProgrammaticStreamSerialization;
    attr[0].val.programmaticStreamSerializationAllowed = 1;

    {   // main: overlaps with rank via PDL
        cudaLaunchConfig_t cfg = {};
        cfg.gridDim = dim3(NTOK / 4);
        cfg.blockDim = dim3(128);
        cfg.dynamicSmemBytes = 0;
        cfg.stream = 0;
        cfg.attrs = attr;
        cfg.numAttrs = 1;
        cudaLaunchKernelEx(&cfg, main_kernel, h, W, bias, wh, accp,
                           weighted, acc);
    }
    {   // pack: launch gap hidden behind main's tail
        cudaLaunchConfig_t cfg = {};
        cfg.gridDim = dim3(NTOK / 4);
        cfg.blockDim = dim3(128);
        cfg.dynamicSmemBytes = 0;
        cfg.stream = 0;
        cfg.attrs = attr;
        cfg.numAttrs = 1;
        cudaLaunchKernelEx(&cfg, pack_kernel, h, packed);
    }
}